// round 14
// baseline (speedup 1.0000x reference)
#include <cuda_runtime.h>
#include <cstdint>

#define N_IN   128
#define N_HID  512
#define N_OUT  128
#define BATCH  128
#define LENGTH 1024
#define M_ROWS (BATCH * LENGTH)
#define T_SEG  256

#define OUT_LIST_OFF  67108864ull
#define OUT_FINAL_OFF 83886080ull

__device__ float g_Weff[N_HID * N_IN];
__device__ float g_beff[N_HID];

// ---------------- W_eff = W_ih @ W_in ; b_eff = W_ih@b_in + b_ih + b_hh -----
__global__ void weff_kernel(const float* __restrict__ Wih,
                            const float* __restrict__ Win,
                            const float* __restrict__ bin,
                            const float* __restrict__ bih,
                            const float* __restrict__ bhh) {
    const int j = blockIdx.x;
    const int i = threadIdx.x;
    __shared__ float sred[128];

    float acc = 0.0f;
    #pragma unroll 8
    for (int k = 0; k < N_HID; k++)
        acc = fmaf(Wih[j * N_HID + k], Win[k * N_IN + i], acc);
    g_Weff[j * N_IN + i] = acc;

    float accb = 0.0f;
    for (int k = i; k < N_HID; k += 128)
        accb = fmaf(Wih[j * N_HID + k], bin[k], accb);
    sred[i] = accb;
    __syncthreads();
    for (int st = 64; st > 0; st >>= 1) {
        if (i < st) sred[i] += sred[i + st];
        __syncthreads();
    }
    if (i == 0) g_beff[j] = sred[0] + bih[j] + bhh[j];
}

// ---------------- C[m][n] = sum_k A[m][k]*B[n][k] + bias[n] -----------------
__global__ __launch_bounds__(256) void gemm_tn_bias(
    const float* __restrict__ A, const float* __restrict__ B,
    const float* __restrict__ bias, float* __restrict__ C,
    int M, int N, int K)
{
    __shared__ float As[8][132];
    __shared__ float Bs[8][132];

    const int tid = threadIdx.x;
    const int m0 = blockIdx.x * 128;
    const int n0 = blockIdx.y * 128;
    const int tx = tid & 15;
    const int ty = tid >> 4;
    const int lr = tid >> 1;
    const int lc = (tid & 1) << 2;

    float acc[8][8];
    #pragma unroll
    for (int i = 0; i < 8; i++)
        #pragma unroll
        for (int j = 0; j < 8; j++) acc[i][j] = 0.0f;

    const float* Ap = &A[(size_t)(m0 + lr) * K + lc];
    const float* Bp = &B[(size_t)(n0 + lr) * K + lc];

    for (int k0 = 0; k0 < K; k0 += 8) {
        float4 av = *(const float4*)&Ap[k0];
        float4 bv = *(const float4*)&Bp[k0];
        As[lc + 0][lr] = av.x; As[lc + 1][lr] = av.y;
        As[lc + 2][lr] = av.z; As[lc + 3][lr] = av.w;
        Bs[lc + 0][lr] = bv.x; Bs[lc + 1][lr] = bv.y;
        Bs[lc + 2][lr] = bv.z; Bs[lc + 3][lr] = bv.w;
        __syncthreads();

        #pragma unroll
        for (int kk = 0; kk < 8; kk++) {
            float4 a0 = *(const float4*)&As[kk][ty * 8];
            float4 a1 = *(const float4*)&As[kk][ty * 8 + 4];
            float4 b0 = *(const float4*)&Bs[kk][tx * 8];
            float4 b1 = *(const float4*)&Bs[kk][tx * 8 + 4];
            float ra[8] = {a0.x, a0.y, a0.z, a0.w, a1.x, a1.y, a1.z, a1.w};
            float rb[8] = {b0.x, b0.y, b0.z, b0.w, b1.x, b1.y, b1.z, b1.w};
            #pragma unroll
            for (int i = 0; i < 8; i++)
                #pragma unroll
                for (int j = 0; j < 8; j++)
                    acc[i][j] = fmaf(ra[i], rb[j], acc[i][j]);
        }
        __syncthreads();
    }

    float bs[8];
    #pragma unroll
    for (int j = 0; j < 8; j++) bs[j] = bias[n0 + tx * 8 + j];

    #pragma unroll
    for (int i = 0; i < 8; i++) {
        float* crow = &C[(size_t)(m0 + ty * 8 + i) * N + n0 + tx * 8];
        *(float4*)&crow[0] = make_float4(acc[i][0] + bs[0], acc[i][1] + bs[1],
                                         acc[i][2] + bs[2], acc[i][3] + bs[3]);
        *(float4*)&crow[4] = make_float4(acc[i][4] + bs[4], acc[i][5] + bs[5],
                                         acc[i][6] + bs[6], acc[i][7] + bs[7]);
    }
}

// ---------------- recurrence: bf16x3 mma, mbarrier split-phase exchange -----
// 16 clusters x 8 CTAs x 256 threads. Warp w: m-tile mt=w&3, k-half kh=w>>2.
// H operand layout: hb[parity][rank: 256 hi words + 256 lo words], word(k2,b)
// hi = (k2>>5)*512 + (k2&31)*8 + b, lo = +256. Push slice = 2KB contiguous.
// Sync: per-buffer mbarriers full[2], count=32 (8 CTAs x 4 warps); per-warp
// release-arrive after its DSMEM stores; acquire try_wait before reads.
// Finalize balanced over all 8 warps (thread = adjacent row-pair x 1 batch).
#define WPST    260
#define WHI_OFF 0
#define WLO_OFF 16640
#define HB_OFF  33280                 // uint32 [2][4096]
#define SCR_OFF 41472                 // float  [1024]
#define STG_OFF 42496                 // uint32 [512]
#define BAR_OFF 43008                 // 2 x u64 mbarriers
#define SM_WORDS 43012                // *4 = 172048 B

__device__ __forceinline__ uint32_t smem_u32(const void* p) {
    uint32_t a;
    asm("{ .reg .u64 t; cvta.to.shared.u64 t, %1; cvt.u32.u64 %0, t; }"
        : "=r"(a) : "l"(p));
    return a;
}
__device__ __forceinline__ uint32_t pack_bf16(float hi_src, float lo_src) {
    uint32_t r;
    asm("cvt.rn.bf16x2.f32 %0, %1, %2;" : "=r"(r) : "f"(hi_src), "f"(lo_src));
    return r;
}
__device__ __forceinline__ void split2(float e, float o,
                                       uint32_t& hiw, uint32_t& low) {
    hiw = pack_bf16(o, e);
    float ef = __uint_as_float(hiw << 16);
    float of = __uint_as_float(hiw & 0xffff0000u);
    low = pack_bf16(o - of, e - ef);
}
__device__ __forceinline__ void mma_bf16(float* d, uint32_t a0, uint32_t a1,
                                         uint32_t a2, uint32_t a3,
                                         uint32_t b0, uint32_t b1) {
    asm volatile(
        "mma.sync.aligned.m16n8k16.row.col.f32.bf16.bf16.f32 "
        "{%0,%1,%2,%3}, {%4,%5,%6,%7}, {%8,%9}, {%0,%1,%2,%3};"
        : "+f"(d[0]), "+f"(d[1]), "+f"(d[2]), "+f"(d[3])
        : "r"(a0), "r"(a1), "r"(a2), "r"(a3), "r"(b0), "r"(b1));
}
__device__ __forceinline__ void bar_wait(uint32_t addr, uint32_t parity) {
    asm volatile(
        "{\n\t.reg .pred P;\n"
        "WL%=:\n\t"
        "mbarrier.try_wait.parity.acquire.cluster.shared::cta.b64 P, [%0], %1, 0x989680;\n\t"
        "@P bra.uni WD%=;\n\t"
        "bra.uni WL%=;\n"
        "WD%=:\n\t}"
        :: "r"(addr), "r"(parity) : "memory");
}

__global__ __cluster_dims__(8, 1, 1) __launch_bounds__(256, 1)
void rec_kernel(const float* __restrict__ Whh, const float* __restrict__ h0,
                float* __restrict__ hidden, float* __restrict__ hfinal,
                int t0)
{
    extern __shared__ float sm[];
    uint32_t* whi = (uint32_t*)sm + WHI_OFF;
    uint32_t* wlo = (uint32_t*)sm + WLO_OFF;
    uint32_t* hb  = (uint32_t*)sm + HB_OFF;    // [2][4096]
    float*    scr = sm + SCR_OFF;              // [1024]
    uint32_t* stg = (uint32_t*)sm + STG_OFF;   // [512]

    const int tid = threadIdx.x;
    uint32_t rank;
    asm("mov.u32 %0, %%cluster_ctarank;" : "=r"(rank));
    const int grp  = blockIdx.x >> 3;
    const int row0 = (int)rank * 64;
    const int b0   = grp * 8;

    const uint32_t barL = smem_u32((char*)sm + BAR_OFF * 4);

    // init mbarriers (count 32 = 8 CTAs x 4 pusher warps)
    if (tid == 0) {
        asm volatile("mbarrier.init.shared.b64 [%0], %1;"
                     :: "r"(barL), "r"(32u) : "memory");
        asm volatile("mbarrier.init.shared.b64 [%0], %1;"
                     :: "r"(barL + 8), "r"(32u) : "memory");
    }

    // one-time W split
    for (int idx = tid; idx < 64 * 256; idx += 256) {
        int r = idx >> 8, k2 = idx & 255;
        float2 wv = *(const float2*)&Whh[(size_t)(row0 + r) * N_HID + 2 * k2];
        uint32_t hw, lw;
        split2(wv.x, wv.y, hw, lw);
        whi[r * WPST + k2] = hw;
        wlo[r * WPST + k2] = lw;
    }
    // prefill parity (t0&1) locally with h(t0-1), full 256 k2 x 8 b
    {
        const int p0 = t0 & 1;
        for (int i = 0; i < 8; i++) {
            int idx = tid + i * 256;           // k2*8 + b over [0,2048)
            int k2 = idx >> 3, b = idx & 7;
            const float* src = (t0 == 0)
                ? &h0[(size_t)(b0 + b) * N_HID + 2 * k2]
                : &hidden[((size_t)(b0 + b) * LENGTH + (t0 - 1)) * N_HID + 2 * k2];
            float2 h = *(const float2*)src;
            uint32_t hw, lw;
            split2(h.x, h.y, hw, lw);
            int word = (k2 >> 5) * 512 + (k2 & 31) * 8 + b;
            hb[p0 * 4096 + word] = hw;
            hb[p0 * 4096 + word + 256] = lw;
        }
    }

    const int w    = tid >> 5;
    const int lane = tid & 31;
    const int mt   = w & 3;
    const int kh   = w >> 2;
    const int g    = lane >> 2;
    const int tg   = lane & 3;

    // A operand pointers
    const uint32_t* wh0 = whi + (mt * 16 + g) * WPST + kh * 128 + tg;
    const uint32_t* wh8 = wh0 + 8 * WPST;
    const uint32_t* wl0 = wlo + (mt * 16 + g) * WPST + kh * 128 + tg;
    const uint32_t* wl8 = wl0 + 8 * WPST;
    // B operand base (per-rank contiguous layout)
    const uint32_t* bbase0 = hb + kh * 2048 + tg * 8 + g;

    // finalize coords: thread = adjacent row pair (r0,r0+1) x batch fb
    const int lk2 = tid >> 3;          // 0..31
    const int fb  = tid & 7;
    const int r0  = lk2 * 2;
    // scr indices (loop-invariant)
    const int mtc = r0 >> 4;
    const int i0  = r0 & 15, i1 = i0 + 1;
    const int idx0 = mtc * 128 + (((i0 & 7) * 4) + (fb >> 1)) * 4
                     + ((i0 >> 3) * 2 + (fb & 1));
    const int idx1 = mtc * 128 + (((i1 & 7) * 4) + (fb >> 1)) * 4
                     + ((i1 >> 3) * 2 + (fb & 1));
    const int absr = row0 + r0;
    const int bg   = b0 + fb;

    // h_old registers (fp32 exact)
    float2 hr;
    {
        const float* src = (t0 == 0)
            ? &h0[(size_t)bg * N_HID + absr]
            : &hidden[((size_t)bg * LENGTH + (t0 - 1)) * N_HID + absr];
        hr = *(const float2*)src;
    }

    // push decomposition: 8 ranks x 128 v4; thread does 4 (ranks rb+2i)
    const int f  = tid & 127;
    const int rb = tid >> 7;
    const uint32_t* pSrc = stg + f * 4;
    const uint32_t slotW = rank * 512 + (uint32_t)f * 4;   // words in parity

    uint32_t Hbase = smem_u32(hb);
    uint32_t peerH[8], peerBar[8];
    #pragma unroll
    for (int r = 0; r < 8; r++) {
        asm("mapa.shared::cluster.u32 %0, %1, %2;"
            : "=r"(peerH[r]) : "r"(Hbase), "r"(r));
        asm("mapa.shared::cluster.u32 %0, %1, %2;"
            : "=r"(peerBar[r]) : "r"(barL), "r"(r));
    }

    __syncthreads();
    // all barriers init'd cluster-wide before any push can arrive
    asm volatile("barrier.cluster.arrive.aligned;" ::: "memory");
    asm volatile("barrier.cluster.wait.aligned;"   ::: "memory");

    const int tend = t0 + T_SEG;
    for (int t = t0; t < tend; t++) {
        const int p = t & 1;
        const int q = p ^ 1;

        // wait for buffer p fill (skip first iter: prefilled locally)
        if (t != t0) {
            uint32_t parity = (uint32_t)(((t - t0 - 1) >> 1) & 1);
            bar_wait(barL + (uint32_t)p * 8, parity);
        }

        // Z prefetch (all threads, float2) — hides under MMA
        size_t off = ((size_t)bg * LENGTH + t) * N_HID + absr;
        float2 z2 = *(const float2*)&hidden[off];

        // MMA mainloop
        const uint32_t* bb = bbase0 + p * 4096;
        float acc0[4] = {0, 0, 0, 0};
        float acc1[4] = {0, 0, 0, 0};
        float acc2[4] = {0, 0, 0, 0};
        #pragma unroll
        for (int ks = 0; ks < 16; ks++) {
            const int boff = (ks >> 2) * 512 + (ks & 3) * 64;
            uint32_t ah0 = wh0[ks * 8],     ah1 = wh8[ks * 8];
            uint32_t ah2 = wh0[ks * 8 + 4], ah3 = wh8[ks * 8 + 4];
            uint32_t al0 = wl0[ks * 8],     al1 = wl8[ks * 8];
            uint32_t al2 = wl0[ks * 8 + 4], al3 = wl8[ks * 8 + 4];
            uint32_t bh0 = bb[boff],       bh1 = bb[boff + 32];
            uint32_t bl0 = bb[boff + 256], bl1 = bb[boff + 288];
            mma_bf16(acc0, ah0, ah1, ah2, ah3, bh0, bh1);
            mma_bf16(acc1, ah0, ah1, ah2, ah3, bl0, bl1);
            mma_bf16(acc2, al0, al1, al2, al3, bh0, bh1);
        }
        // all warps write partials
        {
            float4 cv = make_float4(acc0[0] + acc1[0] + acc2[0],
                                    acc0[1] + acc1[1] + acc2[1],
                                    acc0[2] + acc1[2] + acc2[2],
                                    acc0[3] + acc1[3] + acc2[3]);
            *(float4*)&scr[kh * 512 + mt * 128 + lane * 4] = cv;
        }
        __syncthreads();

        // balanced finalize: every thread owns (r0,r0+1) x fb
        float s0 = scr[idx0] + scr[512 + idx0];
        float s1 = scr[idx1] + scr[512 + idx1];
        float hn0 = 0.9f * hr.x + 0.1f * fmaxf(z2.x + s0, 0.0f);
        float hn1 = 0.9f * hr.y + 0.1f * fmaxf(z2.y + s1, 0.0f);
        hr.x = hn0; hr.y = hn1;
        uint32_t hw, lw;
        split2(hn0, hn1, hw, lw);
        stg[lk2 * 8 + fb] = hw;
        stg[256 + lk2 * 8 + fb] = lw;
        __syncthreads();

        // push slice to 4 ranks' buffer q, then per-warp release-arrive
        const uint32_t dOff = ((uint32_t)q * 4096u + slotW) * 4u;
        uint4 v4 = *(const uint4*)pSrc;
        #pragma unroll
        for (int i = 0; i < 4; i++) {
            int r = rb + 2 * i;
            asm volatile("st.shared::cluster.v4.b32 [%0], {%1,%2,%3,%4};"
                         :: "r"(peerH[r] + dOff),
                            "r"(v4.x), "r"(v4.y), "r"(v4.z), "r"(v4.w)
                         : "memory");
        }
        __syncwarp();
        if (lane == 0) {
            #pragma unroll
            for (int i = 0; i < 4; i++) {
                int r = rb + 2 * i;
                asm volatile(
                    "mbarrier.arrive.release.cluster.shared::cluster.b64 _, [%0];"
                    :: "r"(peerBar[r] + (uint32_t)q * 8u) : "memory");
            }
        }

        // global stores in the exchange shadow
        *(float2*)&hidden[off] = make_float2(hn0, hn1);
        if (t == LENGTH - 1)
            *(float2*)&hfinal[(size_t)bg * N_HID + absr] =
                make_float2(hn0, hn1);
    }

    // keep SMEM alive until all peers' in-flight stores land
    asm volatile("barrier.cluster.arrive.aligned;" ::: "memory");
    asm volatile("barrier.cluster.wait.aligned;"   ::: "memory");
}

extern "C" void kernel_launch(void* const* d_in, const int* in_sizes, int n_in,
                              void* d_out, int out_size) {
    const float* u    = (const float*)d_in[0];
    const float* h0   = (const float*)d_in[1];
    const float* Win  = (const float*)d_in[2];
    const float* bin  = (const float*)d_in[3];
    const float* Wih  = (const float*)d_in[4];
    const float* bih  = (const float*)d_in[5];
    const float* Whh  = (const float*)d_in[6];
    const float* bhh  = (const float*)d_in[7];
    const float* Wout = (const float*)d_in[8];
    const float* bout = (const float*)d_in[9];

    float* out     = (float*)d_out;
    float* hidden  = out;
    float* outlist = out + OUT_LIST_OFF;
    float* hfinal  = out + OUT_FINAL_OFF;

    weff_kernel<<<N_HID, 128>>>(Wih, Win, bin, bih, bhh);

    {
        float* dWeff; float* dbeff;
        cudaGetSymbolAddress((void**)&dWeff, g_Weff);
        cudaGetSymbolAddress((void**)&dbeff, g_beff);
        dim3 grid(M_ROWS / 128, N_HID / 128);
        gemm_tn_bias<<<grid, 256>>>(u, dWeff, dbeff, hidden,
                                    M_ROWS, N_HID, N_IN);
    }

    {
        static int smem_set = 0;
        int smem = SM_WORDS * 4;   // 172048 B
        if (!smem_set) {
            cudaFuncSetAttribute(rec_kernel,
                                 cudaFuncAttributeMaxDynamicSharedMemorySize,
                                 smem);
            smem_set = 1;
        }
        for (int t0 = 0; t0 < LENGTH; t0 += T_SEG)
            rec_kernel<<<128, 256, smem>>>(Whh, h0, hidden, hfinal, t0);
    }

    {
        dim3 grid(M_ROWS / 128, N_OUT / 128);
        gemm_tn_bias<<<grid, 256>>>(hidden, Wout, bout, outlist,
                                    M_ROWS, N_OUT, N_HID);
    }
}

// round 15
// speedup vs baseline: 1.3498x; 1.3498x over previous
#include <cuda_runtime.h>
#include <cstdint>

#define N_IN   128
#define N_HID  512
#define N_OUT  128
#define BATCH  128
#define LENGTH 1024
#define M_ROWS (BATCH * LENGTH)
#define T_SEG  256

#define OUT_LIST_OFF  67108864ull
#define OUT_FINAL_OFF 83886080ull

__device__ float g_Weff[N_HID * N_IN];
__device__ float g_beff[N_HID];

// ---------------- W_eff = W_ih @ W_in ; b_eff = W_ih@b_in + b_ih + b_hh -----
__global__ void weff_kernel(const float* __restrict__ Wih,
                            const float* __restrict__ Win,
                            const float* __restrict__ bin,
                            const float* __restrict__ bih,
                            const float* __restrict__ bhh) {
    const int j = blockIdx.x;
    const int i = threadIdx.x;
    __shared__ float sred[128];

    float acc = 0.0f;
    #pragma unroll 8
    for (int k = 0; k < N_HID; k++)
        acc = fmaf(Wih[j * N_HID + k], Win[k * N_IN + i], acc);
    g_Weff[j * N_IN + i] = acc;

    float accb = 0.0f;
    for (int k = i; k < N_HID; k += 128)
        accb = fmaf(Wih[j * N_HID + k], bin[k], accb);
    sred[i] = accb;
    __syncthreads();
    for (int st = 64; st > 0; st >>= 1) {
        if (i < st) sred[i] += sred[i + st];
        __syncthreads();
    }
    if (i == 0) g_beff[j] = sred[0] + bih[j] + bhh[j];
}

// ---------------- C[m][n] = sum_k A[m][k]*B[n][k] + bias[n] -----------------
__global__ __launch_bounds__(256) void gemm_tn_bias(
    const float* __restrict__ A, const float* __restrict__ B,
    const float* __restrict__ bias, float* __restrict__ C,
    int M, int N, int K)
{
    __shared__ float As[8][132];
    __shared__ float Bs[8][132];

    const int tid = threadIdx.x;
    const int m0 = blockIdx.x * 128;
    const int n0 = blockIdx.y * 128;
    const int tx = tid & 15;
    const int ty = tid >> 4;
    const int lr = tid >> 1;
    const int lc = (tid & 1) << 2;

    float acc[8][8];
    #pragma unroll
    for (int i = 0; i < 8; i++)
        #pragma unroll
        for (int j = 0; j < 8; j++) acc[i][j] = 0.0f;

    const float* Ap = &A[(size_t)(m0 + lr) * K + lc];
    const float* Bp = &B[(size_t)(n0 + lr) * K + lc];

    for (int k0 = 0; k0 < K; k0 += 8) {
        float4 av = *(const float4*)&Ap[k0];
        float4 bv = *(const float4*)&Bp[k0];
        As[lc + 0][lr] = av.x; As[lc + 1][lr] = av.y;
        As[lc + 2][lr] = av.z; As[lc + 3][lr] = av.w;
        Bs[lc + 0][lr] = bv.x; Bs[lc + 1][lr] = bv.y;
        Bs[lc + 2][lr] = bv.z; Bs[lc + 3][lr] = bv.w;
        __syncthreads();

        #pragma unroll
        for (int kk = 0; kk < 8; kk++) {
            float4 a0 = *(const float4*)&As[kk][ty * 8];
            float4 a1 = *(const float4*)&As[kk][ty * 8 + 4];
            float4 b0 = *(const float4*)&Bs[kk][tx * 8];
            float4 b1 = *(const float4*)&Bs[kk][tx * 8 + 4];
            float ra[8] = {a0.x, a0.y, a0.z, a0.w, a1.x, a1.y, a1.z, a1.w};
            float rb[8] = {b0.x, b0.y, b0.z, b0.w, b1.x, b1.y, b1.z, b1.w};
            #pragma unroll
            for (int i = 0; i < 8; i++)
                #pragma unroll
                for (int j = 0; j < 8; j++)
                    acc[i][j] = fmaf(ra[i], rb[j], acc[i][j]);
        }
        __syncthreads();
    }

    float bs[8];
    #pragma unroll
    for (int j = 0; j < 8; j++) bs[j] = bias[n0 + tx * 8 + j];

    #pragma unroll
    for (int i = 0; i < 8; i++) {
        float* crow = &C[(size_t)(m0 + ty * 8 + i) * N + n0 + tx * 8];
        *(float4*)&crow[0] = make_float4(acc[i][0] + bs[0], acc[i][1] + bs[1],
                                         acc[i][2] + bs[2], acc[i][3] + bs[3]);
        *(float4*)&crow[4] = make_float4(acc[i][4] + bs[4], acc[i][5] + bs[5],
                                         acc[i][6] + bs[6], acc[i][7] + bs[7]);
    }
}

// ---------------- recurrence: bf16x3 mma, balanced finalize, cluster bar ----
// 16 clusters x 8 CTAs x 256 threads. Warp w: m-tile mt=w&3, k-half kh=w>>2.
// H operand: hb[parity][4096], per-rank contiguous: word(k2,b) hi =
// (k2>>5)*512 + (k2&31)*8 + b, lo = +256. Push slice 2KB contiguous/rank.
// Finalize balanced over all 8 warps (thread = adjacent row-pair x batch),
// h_old in registers. Sync = one barrier.cluster per step (round-13 proven).
#define WPST    260
#define WHI_OFF 0
#define WLO_OFF 16640
#define HB_OFF  33280                 // uint32 [2][4096]
#define SCR_OFF 41472                 // float  [1024]
#define STG_OFF 42496                 // uint32 [512]
#define SM_WORDS 43008                // *4 = 172032 B

__device__ __forceinline__ uint32_t smem_u32(const void* p) {
    uint32_t a;
    asm("{ .reg .u64 t; cvta.to.shared.u64 t, %1; cvt.u32.u64 %0, t; }"
        : "=r"(a) : "l"(p));
    return a;
}
__device__ __forceinline__ uint32_t pack_bf16(float hi_src, float lo_src) {
    uint32_t r;
    asm("cvt.rn.bf16x2.f32 %0, %1, %2;" : "=r"(r) : "f"(hi_src), "f"(lo_src));
    return r;
}
__device__ __forceinline__ void split2(float e, float o,
                                       uint32_t& hiw, uint32_t& low) {
    hiw = pack_bf16(o, e);
    float ef = __uint_as_float(hiw << 16);
    float of = __uint_as_float(hiw & 0xffff0000u);
    low = pack_bf16(o - of, e - ef);
}
__device__ __forceinline__ void mma_bf16(float* d, uint32_t a0, uint32_t a1,
                                         uint32_t a2, uint32_t a3,
                                         uint32_t b0, uint32_t b1) {
    asm volatile(
        "mma.sync.aligned.m16n8k16.row.col.f32.bf16.bf16.f32 "
        "{%0,%1,%2,%3}, {%4,%5,%6,%7}, {%8,%9}, {%0,%1,%2,%3};"
        : "+f"(d[0]), "+f"(d[1]), "+f"(d[2]), "+f"(d[3])
        : "r"(a0), "r"(a1), "r"(a2), "r"(a3), "r"(b0), "r"(b1));
}

__global__ __cluster_dims__(8, 1, 1) __launch_bounds__(256, 1)
void rec_kernel(const float* __restrict__ Whh, const float* __restrict__ h0,
                float* __restrict__ hidden, float* __restrict__ hfinal,
                int t0)
{
    extern __shared__ float sm[];
    uint32_t* whi = (uint32_t*)sm + WHI_OFF;
    uint32_t* wlo = (uint32_t*)sm + WLO_OFF;
    uint32_t* hb  = (uint32_t*)sm + HB_OFF;    // [2][4096]
    float*    scr = sm + SCR_OFF;              // [1024]
    uint32_t* stg = (uint32_t*)sm + STG_OFF;   // [512]

    const int tid = threadIdx.x;
    uint32_t rank;
    asm("mov.u32 %0, %%cluster_ctarank;" : "=r"(rank));
    const int grp  = blockIdx.x >> 3;
    const int row0 = (int)rank * 64;
    const int b0   = grp * 8;

    // one-time W split
    for (int idx = tid; idx < 64 * 256; idx += 256) {
        int r = idx >> 8, k2 = idx & 255;
        float2 wv = *(const float2*)&Whh[(size_t)(row0 + r) * N_HID + 2 * k2];
        uint32_t hw, lw;
        split2(wv.x, wv.y, hw, lw);
        whi[r * WPST + k2] = hw;
        wlo[r * WPST + k2] = lw;
    }
    // prefill parity (t0&1) locally with h(t0-1)
    {
        const int p0 = t0 & 1;
        for (int i = 0; i < 8; i++) {
            int idx = tid + i * 256;           // k2*8 + b over [0,2048)
            int k2 = idx >> 3, b = idx & 7;
            const float* src = (t0 == 0)
                ? &h0[(size_t)(b0 + b) * N_HID + 2 * k2]
                : &hidden[((size_t)(b0 + b) * LENGTH + (t0 - 1)) * N_HID + 2 * k2];
            float2 h = *(const float2*)src;
            uint32_t hw, lw;
            split2(h.x, h.y, hw, lw);
            int word = (k2 >> 5) * 512 + (k2 & 31) * 8 + b;
            hb[p0 * 4096 + word] = hw;
            hb[p0 * 4096 + word + 256] = lw;
        }
    }

    const int w    = tid >> 5;
    const int lane = tid & 31;
    const int mt   = w & 3;
    const int kh   = w >> 2;
    const int g    = lane >> 2;
    const int tg   = lane & 3;

    // A operand pointers
    const uint32_t* wh0 = whi + (mt * 16 + g) * WPST + kh * 128 + tg;
    const uint32_t* wh8 = wh0 + 8 * WPST;
    const uint32_t* wl0 = wlo + (mt * 16 + g) * WPST + kh * 128 + tg;
    const uint32_t* wl8 = wl0 + 8 * WPST;
    // B operand base (per-rank contiguous layout)
    const uint32_t* bbase0 = hb + kh * 2048 + tg * 8 + g;

    // finalize coords: thread = adjacent row pair (r0,r0+1) x batch fb
    const int lk2 = tid >> 3;          // 0..31
    const int fb  = tid & 7;
    const int r0  = lk2 * 2;
    const int mtc = r0 >> 4;
    const int i0  = r0 & 15, i1 = i0 + 1;
    const int idx0 = mtc * 128 + (((i0 & 7) * 4) + (fb >> 1)) * 4
                     + ((i0 >> 3) * 2 + (fb & 1));
    const int idx1 = mtc * 128 + (((i1 & 7) * 4) + (fb >> 1)) * 4
                     + ((i1 >> 3) * 2 + (fb & 1));
    const int absr = row0 + r0;
    const int bg   = b0 + fb;

    // h_old registers (fp32 exact)
    float2 hr;
    {
        const float* src = (t0 == 0)
            ? &h0[(size_t)bg * N_HID + absr]
            : &hidden[((size_t)bg * LENGTH + (t0 - 1)) * N_HID + absr];
        hr = *(const float2*)src;
    }

    // push decomposition: 8 ranks x 128 v4; thread does 4 (ranks rb+2i)
    const int f  = tid & 127;
    const int rb = tid >> 7;
    const uint32_t* pSrc = stg + f * 4;
    const uint32_t slotW = rank * 512 + (uint32_t)f * 4;

    uint32_t Hbase = smem_u32(hb);
    uint32_t peerH[8];
    #pragma unroll
    for (int r = 0; r < 8; r++)
        asm("mapa.shared::cluster.u32 %0, %1, %2;"
            : "=r"(peerH[r]) : "r"(Hbase), "r"(r));

    __syncthreads();

    const int tend = t0 + T_SEG;
    for (int t = t0; t < tend; t++) {
        const int p = t & 1;
        const int q = p ^ 1;

        // Z prefetch (all threads, float2) — hides under MMA
        size_t off = ((size_t)bg * LENGTH + t) * N_HID + absr;
        float2 z2 = *(const float2*)&hidden[off];

        // MMA mainloop
        const uint32_t* bb = bbase0 + p * 4096;
        float acc0[4] = {0, 0, 0, 0};
        float acc1[4] = {0, 0, 0, 0};
        float acc2[4] = {0, 0, 0, 0};
        #pragma unroll
        for (int ks = 0; ks < 16; ks++) {
            const int boff = (ks >> 2) * 512 + (ks & 3) * 64;
            uint32_t ah0 = wh0[ks * 8],     ah1 = wh8[ks * 8];
            uint32_t ah2 = wh0[ks * 8 + 4], ah3 = wh8[ks * 8 + 4];
            uint32_t al0 = wl0[ks * 8],     al1 = wl8[ks * 8];
            uint32_t al2 = wl0[ks * 8 + 4], al3 = wl8[ks * 8 + 4];
            uint32_t bh0 = bb[boff],       bh1 = bb[boff + 32];
            uint32_t bl0 = bb[boff + 256], bl1 = bb[boff + 288];
            mma_bf16(acc0, ah0, ah1, ah2, ah3, bh0, bh1);
            mma_bf16(acc1, ah0, ah1, ah2, ah3, bl0, bl1);
            mma_bf16(acc2, al0, al1, al2, al3, bh0, bh1);
        }
        {
            float4 cv = make_float4(acc0[0] + acc1[0] + acc2[0],
                                    acc0[1] + acc1[1] + acc2[1],
                                    acc0[2] + acc1[2] + acc2[2],
                                    acc0[3] + acc1[3] + acc2[3]);
            *(float4*)&scr[kh * 512 + mt * 128 + lane * 4] = cv;
        }
        __syncthreads();

        // balanced finalize: every thread owns (r0,r0+1) x fb
        float s0 = scr[idx0] + scr[512 + idx0];
        float s1 = scr[idx1] + scr[512 + idx1];
        float hn0 = 0.9f * hr.x + 0.1f * fmaxf(z2.x + s0, 0.0f);
        float hn1 = 0.9f * hr.y + 0.1f * fmaxf(z2.y + s1, 0.0f);
        hr.x = hn0; hr.y = hn1;
        uint32_t hw, lw;
        split2(hn0, hn1, hw, lw);
        stg[lk2 * 8 + fb] = hw;
        stg[256 + lk2 * 8 + fb] = lw;
        __syncthreads();

        // push slice to 4 ranks' buffer q (other half by rb=1 threads)
        const uint32_t dOff = ((uint32_t)q * 4096u + slotW) * 4u;
        uint4 v4 = *(const uint4*)pSrc;
        #pragma unroll
        for (int i = 0; i < 4; i++) {
            int r = rb + 2 * i;
            asm volatile("st.shared::cluster.v4.b32 [%0], {%1,%2,%3,%4};"
                         :: "r"(peerH[r] + dOff),
                            "r"(v4.x), "r"(v4.y), "r"(v4.z), "r"(v4.w)
                         : "memory");
        }
        asm volatile("barrier.cluster.arrive.aligned;" ::: "memory");

        // global stores in barrier-drain shadow
        *(float2*)&hidden[off] = make_float2(hn0, hn1);
        if (t == LENGTH - 1)
            *(float2*)&hfinal[(size_t)bg * N_HID + absr] =
                make_float2(hn0, hn1);

        asm volatile("barrier.cluster.wait.aligned;" ::: "memory");
    }
}

extern "C" void kernel_launch(void* const* d_in, const int* in_sizes, int n_in,
                              void* d_out, int out_size) {
    const float* u    = (const float*)d_in[0];
    const float* h0   = (const float*)d_in[1];
    const float* Win  = (const float*)d_in[2];
    const float* bin  = (const float*)d_in[3];
    const float* Wih  = (const float*)d_in[4];
    const float* bih  = (const float*)d_in[5];
    const float* Whh  = (const float*)d_in[6];
    const float* bhh  = (const float*)d_in[7];
    const float* Wout = (const float*)d_in[8];
    const float* bout = (const float*)d_in[9];

    float* out     = (float*)d_out;
    float* hidden  = out;
    float* outlist = out + OUT_LIST_OFF;
    float* hfinal  = out + OUT_FINAL_OFF;

    weff_kernel<<<N_HID, 128>>>(Wih, Win, bin, bih, bhh);

    {
        float* dWeff; float* dbeff;
        cudaGetSymbolAddress((void**)&dWeff, g_Weff);
        cudaGetSymbolAddress((void**)&dbeff, g_beff);
        dim3 grid(M_ROWS / 128, N_HID / 128);
        gemm_tn_bias<<<grid, 256>>>(u, dWeff, dbeff, hidden,
                                    M_ROWS, N_HID, N_IN);
    }

    {
        static int smem_set = 0;
        int smem = SM_WORDS * 4;   // 172032 B
        if (!smem_set) {
            cudaFuncSetAttribute(rec_kernel,
                                 cudaFuncAttributeMaxDynamicSharedMemorySize,
                                 smem);
            smem_set = 1;
        }
        for (int t0 = 0; t0 < LENGTH; t0 += T_SEG)
            rec_kernel<<<128, 256, smem>>>(Whh, h0, hidden, hfinal, t0);
    }

    {
        dim3 grid(M_ROWS / 128, N_OUT / 128);
        gemm_tn_bias<<<grid, 256>>>(hidden, Wout, bout, outlist,
                                    M_ROWS, N_OUT, N_HID);
    }
}

// round 16
// speedup vs baseline: 1.4761x; 1.0936x over previous
#include <cuda_runtime.h>
#include <cstdint>

#define N_IN   128
#define N_HID  512
#define N_OUT  128
#define BATCH  128
#define LENGTH 1024
#define M_ROWS (BATCH * LENGTH)
#define T_SEG  256

#define OUT_LIST_OFF  67108864ull
#define OUT_FINAL_OFF 83886080ull

__device__ float g_Weff[N_HID * N_IN];
__device__ float g_beff[N_HID];

__device__ __forceinline__ uint32_t smem_u32(const void* p) {
    uint32_t a;
    asm("{ .reg .u64 t; cvta.to.shared.u64 t, %1; cvt.u32.u64 %0, t; }"
        : "=r"(a) : "l"(p));
    return a;
}
__device__ __forceinline__ uint32_t pack_bf16(float hi_src, float lo_src) {
    uint32_t r;
    asm("cvt.rn.bf16x2.f32 %0, %1, %2;" : "=r"(r) : "f"(hi_src), "f"(lo_src));
    return r;
}
__device__ __forceinline__ void split2(float e, float o,
                                       uint32_t& hiw, uint32_t& low) {
    hiw = pack_bf16(o, e);
    float ef = __uint_as_float(hiw << 16);
    float of = __uint_as_float(hiw & 0xffff0000u);
    low = pack_bf16(o - of, e - ef);
}
__device__ __forceinline__ void mma_bf16(float* d, uint32_t a0, uint32_t a1,
                                         uint32_t a2, uint32_t a3,
                                         uint32_t b0, uint32_t b1) {
    asm volatile(
        "mma.sync.aligned.m16n8k16.row.col.f32.bf16.bf16.f32 "
        "{%0,%1,%2,%3}, {%4,%5,%6,%7}, {%8,%9}, {%0,%1,%2,%3};"
        : "+f"(d[0]), "+f"(d[1]), "+f"(d[2]), "+f"(d[3])
        : "r"(a0), "r"(a1), "r"(a2), "r"(a3), "r"(b0), "r"(b1));
}

// ---------------- W_eff = W_ih @ W_in ; b_eff = W_ih@b_in + b_ih + b_hh -----
__global__ void weff_kernel(const float* __restrict__ Wih,
                            const float* __restrict__ Win,
                            const float* __restrict__ bin,
                            const float* __restrict__ bih,
                            const float* __restrict__ bhh) {
    const int j = blockIdx.x;
    const int i = threadIdx.x;
    __shared__ float sred[128];

    float acc = 0.0f;
    #pragma unroll 8
    for (int k = 0; k < N_HID; k++)
        acc = fmaf(Wih[j * N_HID + k], Win[k * N_IN + i], acc);
    g_Weff[j * N_IN + i] = acc;

    float accb = 0.0f;
    for (int k = i; k < N_HID; k += 128)
        accb = fmaf(Wih[j * N_HID + k], bin[k], accb);
    sred[i] = accb;
    __syncthreads();
    for (int st = 64; st > 0; st >>= 1) {
        if (i < st) sred[i] += sred[i + st];
        __syncthreads();
    }
    if (i == 0) g_beff[j] = sred[0] + bih[j] + bhh[j];
}

// ---------------- bf16x3 tensor GEMM: C[m][n] = A[m][:]·B[n][:] + bias[n] ---
// Block tile 128(M) x 64(N) x 32(K); 8 warps (4 m x 2 n), warp tile 32x32.
// A,B split to packed bf16 hi/lo in SMEM; 3 MMAs (hh, hl, lh) per product.
#define AST 20     // a smem row stride (words: 16 k2 + 4 pad) -> banks distinct
#define BST 72     // b smem k2-row stride (words)             -> banks distinct

__global__ __launch_bounds__(256) void gemm_bf16x3(
    const float* __restrict__ A, const float* __restrict__ B,
    const float* __restrict__ bias, float* __restrict__ C,
    int M, int N, int K)
{
    __shared__ uint32_t a_hi[128 * AST];
    __shared__ uint32_t a_lo[128 * AST];
    __shared__ uint32_t b_hi[16 * BST];
    __shared__ uint32_t b_lo[16 * BST];

    const int tid   = threadIdx.x;
    const int warp  = tid >> 5;
    const int lane  = tid & 31;
    const int warpM = warp & 3;
    const int warpN = warp >> 2;
    const int g     = lane >> 2;
    const int tg    = lane & 3;

    const int m0 = blockIdx.x * 128;
    const int n0 = blockIdx.y * 64;

    float c[2][4][4];
    #pragma unroll
    for (int mf = 0; mf < 2; mf++)
        #pragma unroll
        for (int nf = 0; nf < 4; nf++)
            #pragma unroll
            for (int i = 0; i < 4; i++) c[mf][nf][i] = 0.0f;

    for (int kt = 0; kt < K; kt += 32) {
        __syncthreads();
        // load + split A tile (128 x 32)
        #pragma unroll
        for (int i = 0; i < 4; i++) {
            int idx = tid + i * 256;          // 0..1023 float4s
            int row = idx >> 3, f4 = idx & 7;
            float4 v = *(const float4*)&A[(size_t)(m0 + row) * K + kt + f4 * 4];
            uint32_t h0, l0, h1, l1;
            split2(v.x, v.y, h0, l0);
            split2(v.z, v.w, h1, l1);
            a_hi[row * AST + f4 * 2]     = h0;
            a_hi[row * AST + f4 * 2 + 1] = h1;
            a_lo[row * AST + f4 * 2]     = l0;
            a_lo[row * AST + f4 * 2 + 1] = l1;
        }
        // load + split B tile (64 x 32), store transposed [k2][n]
        #pragma unroll
        for (int i = 0; i < 2; i++) {
            int idx = tid + i * 256;          // 0..511
            int row = idx >> 3, f4 = idx & 7;
            float4 v = *(const float4*)&B[(size_t)(n0 + row) * K + kt + f4 * 4];
            uint32_t h0, l0, h1, l1;
            split2(v.x, v.y, h0, l0);
            split2(v.z, v.w, h1, l1);
            b_hi[(f4 * 2) * BST + row]     = h0;
            b_hi[(f4 * 2 + 1) * BST + row] = h1;
            b_lo[(f4 * 2) * BST + row]     = l0;
            b_lo[(f4 * 2 + 1) * BST + row] = l1;
        }
        __syncthreads();

        #pragma unroll
        for (int ks = 0; ks < 2; ks++) {
            uint32_t ah[2][4], al[2][4];
            #pragma unroll
            for (int mf = 0; mf < 2; mf++) {
                int rb = warpM * 32 + mf * 16;
                ah[mf][0] = a_hi[(rb + g) * AST + ks * 8 + tg];
                ah[mf][1] = a_hi[(rb + g + 8) * AST + ks * 8 + tg];
                ah[mf][2] = a_hi[(rb + g) * AST + ks * 8 + tg + 4];
                ah[mf][3] = a_hi[(rb + g + 8) * AST + ks * 8 + tg + 4];
                al[mf][0] = a_lo[(rb + g) * AST + ks * 8 + tg];
                al[mf][1] = a_lo[(rb + g + 8) * AST + ks * 8 + tg];
                al[mf][2] = a_lo[(rb + g) * AST + ks * 8 + tg + 4];
                al[mf][3] = a_lo[(rb + g + 8) * AST + ks * 8 + tg + 4];
            }
            #pragma unroll
            for (int nf = 0; nf < 4; nf++) {
                int cb = warpN * 32 + nf * 8;
                uint32_t bh0 = b_hi[(ks * 8 + tg) * BST + cb + g];
                uint32_t bh1 = b_hi[(ks * 8 + tg + 4) * BST + cb + g];
                uint32_t bl0 = b_lo[(ks * 8 + tg) * BST + cb + g];
                uint32_t bl1 = b_lo[(ks * 8 + tg + 4) * BST + cb + g];
                #pragma unroll
                for (int mf = 0; mf < 2; mf++) {
                    mma_bf16(c[mf][nf], ah[mf][0], ah[mf][1],
                             ah[mf][2], ah[mf][3], bh0, bh1);
                    mma_bf16(c[mf][nf], ah[mf][0], ah[mf][1],
                             ah[mf][2], ah[mf][3], bl0, bl1);
                    mma_bf16(c[mf][nf], al[mf][0], al[mf][1],
                             al[mf][2], al[mf][3], bh0, bh1);
                }
            }
        }
    }

    // epilogue: c[mf][nf] -> rows (m0+warpM*32+mf*16) + g/(g+8),
    //           cols (n0+warpN*32+nf*8) + 2tg, 2tg+1
    #pragma unroll
    for (int nf = 0; nf < 4; nf++) {
        int col = n0 + warpN * 32 + nf * 8 + 2 * tg;
        float2 bv = *(const float2*)&bias[col];
        #pragma unroll
        for (int mf = 0; mf < 2; mf++) {
            int row = m0 + warpM * 32 + mf * 16 + g;
            *(float2*)&C[(size_t)row * N + col] =
                make_float2(c[mf][nf][0] + bv.x, c[mf][nf][1] + bv.y);
            *(float2*)&C[(size_t)(row + 8) * N + col] =
                make_float2(c[mf][nf][2] + bv.x, c[mf][nf][3] + bv.y);
        }
    }
}

// ---------------- recurrence: bf16x3 mma (round-15, unchanged) --------------
#define WPST    260
#define WHI_OFF 0
#define WLO_OFF 16640
#define HB_OFF  33280                 // uint32 [2][4096]
#define SCR_OFF 41472                 // float  [1024]
#define STG_OFF 42496                 // uint32 [512]
#define SM_WORDS 43008                // *4 = 172032 B

__global__ __cluster_dims__(8, 1, 1) __launch_bounds__(256, 1)
void rec_kernel(const float* __restrict__ Whh, const float* __restrict__ h0,
                float* __restrict__ hidden, float* __restrict__ hfinal,
                int t0)
{
    extern __shared__ float sm[];
    uint32_t* whi = (uint32_t*)sm + WHI_OFF;
    uint32_t* wlo = (uint32_t*)sm + WLO_OFF;
    uint32_t* hb  = (uint32_t*)sm + HB_OFF;
    float*    scr = sm + SCR_OFF;
    uint32_t* stg = (uint32_t*)sm + STG_OFF;

    const int tid = threadIdx.x;
    uint32_t rank;
    asm("mov.u32 %0, %%cluster_ctarank;" : "=r"(rank));
    const int grp  = blockIdx.x >> 3;
    const int row0 = (int)rank * 64;
    const int b0   = grp * 8;

    for (int idx = tid; idx < 64 * 256; idx += 256) {
        int r = idx >> 8, k2 = idx & 255;
        float2 wv = *(const float2*)&Whh[(size_t)(row0 + r) * N_HID + 2 * k2];
        uint32_t hw, lw;
        split2(wv.x, wv.y, hw, lw);
        whi[r * WPST + k2] = hw;
        wlo[r * WPST + k2] = lw;
    }
    {
        const int p0 = t0 & 1;
        for (int i = 0; i < 8; i++) {
            int idx = tid + i * 256;
            int k2 = idx >> 3, b = idx & 7;
            const float* src = (t0 == 0)
                ? &h0[(size_t)(b0 + b) * N_HID + 2 * k2]
                : &hidden[((size_t)(b0 + b) * LENGTH + (t0 - 1)) * N_HID + 2 * k2];
            float2 h = *(const float2*)src;
            uint32_t hw, lw;
            split2(h.x, h.y, hw, lw);
            int word = (k2 >> 5) * 512 + (k2 & 31) * 8 + b;
            hb[p0 * 4096 + word] = hw;
            hb[p0 * 4096 + word + 256] = lw;
        }
    }

    const int w    = tid >> 5;
    const int lane = tid & 31;
    const int mt   = w & 3;
    const int kh   = w >> 2;
    const int g    = lane >> 2;
    const int tg   = lane & 3;

    const uint32_t* wh0 = whi + (mt * 16 + g) * WPST + kh * 128 + tg;
    const uint32_t* wh8 = wh0 + 8 * WPST;
    const uint32_t* wl0 = wlo + (mt * 16 + g) * WPST + kh * 128 + tg;
    const uint32_t* wl8 = wl0 + 8 * WPST;
    const uint32_t* bbase0 = hb + kh * 2048 + tg * 8 + g;

    const int lk2 = tid >> 3;
    const int fb  = tid & 7;
    const int r0  = lk2 * 2;
    const int mtc = r0 >> 4;
    const int i0  = r0 & 15, i1 = i0 + 1;
    const int idx0 = mtc * 128 + (((i0 & 7) * 4) + (fb >> 1)) * 4
                     + ((i0 >> 3) * 2 + (fb & 1));
    const int idx1 = mtc * 128 + (((i1 & 7) * 4) + (fb >> 1)) * 4
                     + ((i1 >> 3) * 2 + (fb & 1));
    const int absr = row0 + r0;
    const int bg   = b0 + fb;

    float2 hr;
    {
        const float* src = (t0 == 0)
            ? &h0[(size_t)bg * N_HID + absr]
            : &hidden[((size_t)bg * LENGTH + (t0 - 1)) * N_HID + absr];
        hr = *(const float2*)src;
    }

    const int f  = tid & 127;
    const int rb = tid >> 7;
    const uint32_t* pSrc = stg + f * 4;
    const uint32_t slotW = rank * 512 + (uint32_t)f * 4;

    uint32_t Hbase = smem_u32(hb);
    uint32_t peerH[8];
    #pragma unroll
    for (int r = 0; r < 8; r++)
        asm("mapa.shared::cluster.u32 %0, %1, %2;"
            : "=r"(peerH[r]) : "r"(Hbase), "r"(r));

    __syncthreads();

    const int tend = t0 + T_SEG;
    for (int t = t0; t < tend; t++) {
        const int p = t & 1;
        const int q = p ^ 1;

        size_t off = ((size_t)bg * LENGTH + t) * N_HID + absr;
        float2 z2 = *(const float2*)&hidden[off];

        const uint32_t* bb = bbase0 + p * 4096;
        float acc0[4] = {0, 0, 0, 0};
        float acc1[4] = {0, 0, 0, 0};
        float acc2[4] = {0, 0, 0, 0};
        #pragma unroll
        for (int ks = 0; ks < 16; ks++) {
            const int boff = (ks >> 2) * 512 + (ks & 3) * 64;
            uint32_t ah0 = wh0[ks * 8],     ah1 = wh8[ks * 8];
            uint32_t ah2 = wh0[ks * 8 + 4], ah3 = wh8[ks * 8 + 4];
            uint32_t al0 = wl0[ks * 8],     al1 = wl8[ks * 8];
            uint32_t al2 = wl0[ks * 8 + 4], al3 = wl8[ks * 8 + 4];
            uint32_t bh0 = bb[boff],       bh1 = bb[boff + 32];
            uint32_t bl0 = bb[boff + 256], bl1 = bb[boff + 288];
            mma_bf16(acc0, ah0, ah1, ah2, ah3, bh0, bh1);
            mma_bf16(acc1, ah0, ah1, ah2, ah3, bl0, bl1);
            mma_bf16(acc2, al0, al1, al2, al3, bh0, bh1);
        }
        {
            float4 cv = make_float4(acc0[0] + acc1[0] + acc2[0],
                                    acc0[1] + acc1[1] + acc2[1],
                                    acc0[2] + acc1[2] + acc2[2],
                                    acc0[3] + acc1[3] + acc2[3]);
            *(float4*)&scr[kh * 512 + mt * 128 + lane * 4] = cv;
        }
        __syncthreads();

        float s0 = scr[idx0] + scr[512 + idx0];
        float s1 = scr[idx1] + scr[512 + idx1];
        float hn0 = 0.9f * hr.x + 0.1f * fmaxf(z2.x + s0, 0.0f);
        float hn1 = 0.9f * hr.y + 0.1f * fmaxf(z2.y + s1, 0.0f);
        hr.x = hn0; hr.y = hn1;
        uint32_t hw, lw;
        split2(hn0, hn1, hw, lw);
        stg[lk2 * 8 + fb] = hw;
        stg[256 + lk2 * 8 + fb] = lw;
        __syncthreads();

        const uint32_t dOff = ((uint32_t)q * 4096u + slotW) * 4u;
        uint4 v4 = *(const uint4*)pSrc;
        #pragma unroll
        for (int i = 0; i < 4; i++) {
            int r = rb + 2 * i;
            asm volatile("st.shared::cluster.v4.b32 [%0], {%1,%2,%3,%4};"
                         :: "r"(peerH[r] + dOff),
                            "r"(v4.x), "r"(v4.y), "r"(v4.z), "r"(v4.w)
                         : "memory");
        }
        asm volatile("barrier.cluster.arrive.aligned;" ::: "memory");

        *(float2*)&hidden[off] = make_float2(hn0, hn1);
        if (t == LENGTH - 1)
            *(float2*)&hfinal[(size_t)bg * N_HID + absr] =
                make_float2(hn0, hn1);

        asm volatile("barrier.cluster.wait.aligned;" ::: "memory");
    }
}

extern "C" void kernel_launch(void* const* d_in, const int* in_sizes, int n_in,
                              void* d_out, int out_size) {
    const float* u    = (const float*)d_in[0];
    const float* h0   = (const float*)d_in[1];
    const float* Win  = (const float*)d_in[2];
    const float* bin  = (const float*)d_in[3];
    const float* Wih  = (const float*)d_in[4];
    const float* bih  = (const float*)d_in[5];
    const float* Whh  = (const float*)d_in[6];
    const float* bhh  = (const float*)d_in[7];
    const float* Wout = (const float*)d_in[8];
    const float* bout = (const float*)d_in[9];

    float* out     = (float*)d_out;
    float* hidden  = out;
    float* outlist = out + OUT_LIST_OFF;
    float* hfinal  = out + OUT_FINAL_OFF;

    weff_kernel<<<N_HID, 128>>>(Wih, Win, bin, bih, bhh);

    // Z = U @ W_eff^T + b_eff  (bf16x3 tensor GEMM)
    {
        float* dWeff; float* dbeff;
        cudaGetSymbolAddress((void**)&dWeff, g_Weff);
        cudaGetSymbolAddress((void**)&dbeff, g_beff);
        dim3 grid(M_ROWS / 128, N_HID / 64);
        gemm_bf16x3<<<grid, 256>>>(u, dWeff, dbeff, hidden,
                                   M_ROWS, N_HID, N_IN);
    }

    // recurrence (unchanged)
    {
        static int smem_set = 0;
        int smem = SM_WORDS * 4;   // 172032 B
        if (!smem_set) {
            cudaFuncSetAttribute(rec_kernel,
                                 cudaFuncAttributeMaxDynamicSharedMemorySize,
                                 smem);
            smem_set = 1;
        }
        for (int t0 = 0; t0 < LENGTH; t0 += T_SEG)
            rec_kernel<<<128, 256, smem>>>(Whh, h0, hidden, hfinal, t0);
    }

    // output_list = hidden_list @ W_out^T + b_out  (bf16x3 tensor GEMM)
    {
        dim3 grid(M_ROWS / 128, N_OUT / 64);
        gemm_bf16x3<<<grid, 256>>>(hidden, Wout, bout, outlist,
                                   M_ROWS, N_OUT, N_HID);
    }
}

// round 17
// speedup vs baseline: 1.7966x; 1.2171x over previous
#include <cuda_runtime.h>
#include <cstdint>

#define N_IN   128
#define N_HID  512
#define N_OUT  128
#define BATCH  128
#define LENGTH 1024
#define M_ROWS (BATCH * LENGTH)
#define T_SEG  256

#define OUT_LIST_OFF  67108864ull
#define OUT_FINAL_OFF 83886080ull

__device__ float g_Weff[N_HID * N_IN];
__device__ float g_beff[N_HID];

__device__ __forceinline__ uint32_t smem_u32(const void* p) {
    uint32_t a;
    asm("{ .reg .u64 t; cvta.to.shared.u64 t, %1; cvt.u32.u64 %0, t; }"
        : "=r"(a) : "l"(p));
    return a;
}
__device__ __forceinline__ uint32_t pack_bf16(float hi_src, float lo_src) {
    uint32_t r;
    asm("cvt.rn.bf16x2.f32 %0, %1, %2;" : "=r"(r) : "f"(hi_src), "f"(lo_src));
    return r;
}
__device__ __forceinline__ void split2(float e, float o,
                                       uint32_t& hiw, uint32_t& low) {
    hiw = pack_bf16(o, e);
    float ef = __uint_as_float(hiw << 16);
    float of = __uint_as_float(hiw & 0xffff0000u);
    low = pack_bf16(o - of, e - ef);
}
__device__ __forceinline__ void mma_bf16(float* d, uint32_t a0, uint32_t a1,
                                         uint32_t a2, uint32_t a3,
                                         uint32_t b0, uint32_t b1) {
    asm volatile(
        "mma.sync.aligned.m16n8k16.row.col.f32.bf16.bf16.f32 "
        "{%0,%1,%2,%3}, {%4,%5,%6,%7}, {%8,%9}, {%0,%1,%2,%3};"
        : "+f"(d[0]), "+f"(d[1]), "+f"(d[2]), "+f"(d[3])
        : "r"(a0), "r"(a1), "r"(a2), "r"(a3), "r"(b0), "r"(b1));
}

// ---------------- W_eff = W_ih @ W_in ; b_eff = W_ih@b_in + b_ih + b_hh -----
__global__ void weff_kernel(const float* __restrict__ Wih,
                            const float* __restrict__ Win,
                            const float* __restrict__ bin,
                            const float* __restrict__ bih,
                            const float* __restrict__ bhh) {
    const int j = blockIdx.x;
    const int i = threadIdx.x;
    __shared__ float sred[128];

    float acc = 0.0f;
    #pragma unroll 8
    for (int k = 0; k < N_HID; k++)
        acc = fmaf(Wih[j * N_HID + k], Win[k * N_IN + i], acc);
    g_Weff[j * N_IN + i] = acc;

    float accb = 0.0f;
    for (int k = i; k < N_HID; k += 128)
        accb = fmaf(Wih[j * N_HID + k], bin[k], accb);
    sred[i] = accb;
    __syncthreads();
    for (int st = 64; st > 0; st >>= 1) {
        if (i < st) sred[i] += sred[i + st];
        __syncthreads();
    }
    if (i == 0) g_beff[j] = sred[0] + bih[j] + bhh[j];
}

// ---------------- bf16x3 tensor GEMM (round-16, unchanged) ------------------
#define AST 20
#define BST 72

__global__ __launch_bounds__(256) void gemm_bf16x3(
    const float* __restrict__ A, const float* __restrict__ B,
    const float* __restrict__ bias, float* __restrict__ C,
    int M, int N, int K)
{
    __shared__ uint32_t a_hi[128 * AST];
    __shared__ uint32_t a_lo[128 * AST];
    __shared__ uint32_t b_hi[16 * BST];
    __shared__ uint32_t b_lo[16 * BST];

    const int tid   = threadIdx.x;
    const int warp  = tid >> 5;
    const int lane  = tid & 31;
    const int warpM = warp & 3;
    const int warpN = warp >> 2;
    const int g     = lane >> 2;
    const int tg    = lane & 3;

    const int m0 = blockIdx.x * 128;
    const int n0 = blockIdx.y * 64;

    float c[2][4][4];
    #pragma unroll
    for (int mf = 0; mf < 2; mf++)
        #pragma unroll
        for (int nf = 0; nf < 4; nf++)
            #pragma unroll
            for (int i = 0; i < 4; i++) c[mf][nf][i] = 0.0f;

    for (int kt = 0; kt < K; kt += 32) {
        __syncthreads();
        #pragma unroll
        for (int i = 0; i < 4; i++) {
            int idx = tid + i * 256;
            int row = idx >> 3, f4 = idx & 7;
            float4 v = *(const float4*)&A[(size_t)(m0 + row) * K + kt + f4 * 4];
            uint32_t h0, l0, h1, l1;
            split2(v.x, v.y, h0, l0);
            split2(v.z, v.w, h1, l1);
            a_hi[row * AST + f4 * 2]     = h0;
            a_hi[row * AST + f4 * 2 + 1] = h1;
            a_lo[row * AST + f4 * 2]     = l0;
            a_lo[row * AST + f4 * 2 + 1] = l1;
        }
        #pragma unroll
        for (int i = 0; i < 2; i++) {
            int idx = tid + i * 256;
            int row = idx >> 3, f4 = idx & 7;
            float4 v = *(const float4*)&B[(size_t)(n0 + row) * K + kt + f4 * 4];
            uint32_t h0, l0, h1, l1;
            split2(v.x, v.y, h0, l0);
            split2(v.z, v.w, h1, l1);
            b_hi[(f4 * 2) * BST + row]     = h0;
            b_hi[(f4 * 2 + 1) * BST + row] = h1;
            b_lo[(f4 * 2) * BST + row]     = l0;
            b_lo[(f4 * 2 + 1) * BST + row] = l1;
        }
        __syncthreads();

        #pragma unroll
        for (int ks = 0; ks < 2; ks++) {
            uint32_t ah[2][4], al[2][4];
            #pragma unroll
            for (int mf = 0; mf < 2; mf++) {
                int rb = warpM * 32 + mf * 16;
                ah[mf][0] = a_hi[(rb + g) * AST + ks * 8 + tg];
                ah[mf][1] = a_hi[(rb + g + 8) * AST + ks * 8 + tg];
                ah[mf][2] = a_hi[(rb + g) * AST + ks * 8 + tg + 4];
                ah[mf][3] = a_hi[(rb + g + 8) * AST + ks * 8 + tg + 4];
                al[mf][0] = a_lo[(rb + g) * AST + ks * 8 + tg];
                al[mf][1] = a_lo[(rb + g + 8) * AST + ks * 8 + tg];
                al[mf][2] = a_lo[(rb + g) * AST + ks * 8 + tg + 4];
                al[mf][3] = a_lo[(rb + g + 8) * AST + ks * 8 + tg + 4];
            }
            #pragma unroll
            for (int nf = 0; nf < 4; nf++) {
                int cb = warpN * 32 + nf * 8;
                uint32_t bh0 = b_hi[(ks * 8 + tg) * BST + cb + g];
                uint32_t bh1 = b_hi[(ks * 8 + tg + 4) * BST + cb + g];
                uint32_t bl0 = b_lo[(ks * 8 + tg) * BST + cb + g];
                uint32_t bl1 = b_lo[(ks * 8 + tg + 4) * BST + cb + g];
                #pragma unroll
                for (int mf = 0; mf < 2; mf++) {
                    mma_bf16(c[mf][nf], ah[mf][0], ah[mf][1],
                             ah[mf][2], ah[mf][3], bh0, bh1);
                    mma_bf16(c[mf][nf], ah[mf][0], ah[mf][1],
                             ah[mf][2], ah[mf][3], bl0, bl1);
                    mma_bf16(c[mf][nf], al[mf][0], al[mf][1],
                             al[mf][2], al[mf][3], bh0, bh1);
                }
            }
        }
    }

    #pragma unroll
    for (int nf = 0; nf < 4; nf++) {
        int col = n0 + warpN * 32 + nf * 8 + 2 * tg;
        float2 bv = *(const float2*)&bias[col];
        #pragma unroll
        for (int mf = 0; mf < 2; mf++) {
            int row = m0 + warpM * 32 + mf * 16 + g;
            *(float2*)&C[(size_t)row * N + col] =
                make_float2(c[mf][nf][0] + bv.x, c[mf][nf][1] + bv.y);
            *(float2*)&C[(size_t)(row + 8) * N + col] =
                make_float2(c[mf][nf][2] + bv.x, c[mf][nf][3] + bv.y);
        }
    }
}

// ---------------- recurrence: W in registers, fragment-layout exchange ------
// 16 clusters x 8 CTAs x 512 threads (16 warps = 4 mt x 4 kh quarters).
// A (W) fragments loaded once from GMEM into registers (8 ks x 4 hi + 4 lo).
// H exchanged in MMA B-fragment order: hb[parity][ (kh*8+ks)*32+lane ][4] =
// {b0h, b0l, b1h, b1l}; rank r's produced slice = words [r*512, r*512+512).
// Per step: 8 uint4 LDS + 24 MMA per thread; 4-way kh scratch reduce;
// finalize on tid<256 (row-pair x batch); one barrier.cluster per step.
#define HB_OFF  0                     // uint32 [2][4096]
#define SCR_OFF 8192                  // float  [2048]
#define STG_OFF 10240                 // uint32 [512]
#define SM_WORDS 10752                // *4 = 43008 B

__global__ __cluster_dims__(8, 1, 1) __launch_bounds__(512, 1)
void rec_kernel(const float* __restrict__ Whh, const float* __restrict__ h0,
                float* __restrict__ hidden, float* __restrict__ hfinal,
                int t0)
{
    extern __shared__ float sm[];
    uint32_t* hb  = (uint32_t*)sm + HB_OFF;
    float*    scr = sm + SCR_OFF;
    uint32_t* stg = (uint32_t*)sm + STG_OFF;

    const int tid = threadIdx.x;
    uint32_t rank;
    asm("mov.u32 %0, %%cluster_ctarank;" : "=r"(rank));
    const int grp  = blockIdx.x >> 3;
    const int row0 = (int)rank * 64;
    const int b0   = grp * 8;

    const int w    = tid >> 5;
    const int lane = tid & 31;
    const int mt   = w & 3;
    const int kh   = w >> 2;     // k-quarter 0..3
    const int g    = lane >> 2;
    const int tg   = lane & 3;

    // ---- one-time W fragment load (GMEM -> registers) ----
    uint32_t Ah[8][4], Al[8][4];
    {
        const int r = row0 + mt * 16 + g;
        const float* Wr  = Whh + (size_t)r * N_HID + kh * 128 + 2 * tg;
        const float* Wr8 = Wr + 8 * N_HID;
        #pragma unroll
        for (int ks = 0; ks < 8; ks++) {
            float2 v0 = *(const float2*)&Wr[ks * 16];
            float2 v1 = *(const float2*)&Wr8[ks * 16];
            float2 v2 = *(const float2*)&Wr[ks * 16 + 8];
            float2 v3 = *(const float2*)&Wr8[ks * 16 + 8];
            split2(v0.x, v0.y, Ah[ks][0], Al[ks][0]);
            split2(v1.x, v1.y, Ah[ks][1], Al[ks][1]);
            split2(v2.x, v2.y, Ah[ks][2], Al[ks][2]);
            split2(v3.x, v3.y, Ah[ks][3], Al[ks][3]);
        }
    }

    // ---- prefill hb[parity t0&1] with h(t0-1) in fragment layout ----
    {
        const int p0 = t0 & 1;
        #pragma unroll
        for (int i = 0; i < 4; i++) {
            int idx = tid + i * 512;          // k2*8 + b over [0,2048)
            int k2 = idx >> 3, b = idx & 7;
            const float* src = (t0 == 0)
                ? &h0[(size_t)(b0 + b) * N_HID + 2 * k2]
                : &hidden[((size_t)(b0 + b) * LENGTH + (t0 - 1)) * N_HID + 2 * k2];
            float2 h = *(const float2*)src;
            uint32_t hw, lw;
            split2(h.x, h.y, hw, lw);
            int khh = k2 >> 6, k2q = k2 & 63;
            int ks = k2q >> 3, qq = k2q & 7;
            int tgq = qq & 3, slot = qq >> 2;
            int word = (((khh * 8 + ks) * 32) + b * 4 + tgq) * 4 + slot * 2;
            hb[p0 * 4096 + word]     = hw;
            hb[p0 * 4096 + word + 1] = lw;
        }
    }

    // ---- finalize coords (tid < 256): row pair (r0, r0+1) x batch fb ----
    const int lk2 = tid >> 3;            // valid for tid<256
    const int fb  = tid & 7;
    const int r0  = lk2 * 2;
    const int mtc = r0 >> 4;
    const int i0  = r0 & 15, i1 = i0 + 1;
    const int idx0 = mtc * 128 + (((i0 & 7) * 4) + (fb >> 1)) * 4
                     + ((i0 >> 3) * 2 + (fb & 1));
    const int idx1 = mtc * 128 + (((i1 & 7) * 4) + (fb >> 1)) * 4
                     + ((i1 >> 3) * 2 + (fb & 1));
    const int absr = row0 + r0;
    const int bg   = b0 + fb;
    // staging address for (lk2, fb): slice-internal fragment position
    const int ksl  = lk2 >> 3, qq2 = lk2 & 7;
    const int tg2  = qq2 & 3,  slt = qq2 >> 2;
    const int stga = (ksl * 32 + fb * 4 + tg2) * 4 + slt * 2;

    float2 hr = make_float2(0.f, 0.f);
    if (tid < 256) {
        const float* src = (t0 == 0)
            ? &h0[(size_t)bg * N_HID + absr]
            : &hidden[((size_t)bg * LENGTH + (t0 - 1)) * N_HID + absr];
        hr = *(const float2*)src;
    }

    // ---- push decomposition: 8 ranks x 128 v4; thread does 2 ----
    const int f4  = tid & 127;
    const int rk0 = tid >> 7;            // 0..3 -> ranks rk0, rk0+4
    const uint32_t* pSrc = stg + f4 * 4;
    const uint32_t slotW = rank * 512 + (uint32_t)f4 * 4;

    uint32_t Hbase = smem_u32(hb);
    uint32_t peerH[8];
    #pragma unroll
    for (int r = 0; r < 8; r++)
        asm("mapa.shared::cluster.u32 %0, %1, %2;"
            : "=r"(peerH[r]) : "r"(Hbase), "r"(r));

    __syncthreads();

    // B fragment base for this warp
    const uint32_t* bfw = hb + kh * 1024 + lane * 4;

    const int tend = t0 + T_SEG;
    for (int t = t0; t < tend; t++) {
        const int p = t & 1;
        const int q = p ^ 1;

        // Z prefetch (finalize threads) — hides under MMA
        size_t off = 0;
        float2 z2 = make_float2(0.f, 0.f);
        if (tid < 256) {
            off = ((size_t)bg * LENGTH + t) * N_HID + absr;
            z2 = *(const float2*)&hidden[off];
        }

        // MMA mainloop: 8 ks, one uint4 B load each
        const uint32_t* bf = bfw + p * 4096;
        float acc0[4] = {0, 0, 0, 0};
        float acc1[4] = {0, 0, 0, 0};
        float acc2[4] = {0, 0, 0, 0};
        #pragma unroll
        for (int ks = 0; ks < 8; ks++) {
            uint4 B = *(const uint4*)(bf + ks * 128);
            mma_bf16(acc0, Ah[ks][0], Ah[ks][1], Ah[ks][2], Ah[ks][3],
                     B.x, B.z);
            mma_bf16(acc1, Ah[ks][0], Ah[ks][1], Ah[ks][2], Ah[ks][3],
                     B.y, B.w);
            mma_bf16(acc2, Al[ks][0], Al[ks][1], Al[ks][2], Al[ks][3],
                     B.x, B.z);
        }
        *(float4*)&scr[kh * 512 + mt * 128 + lane * 4] =
            make_float4(acc0[0] + acc1[0] + acc2[0],
                        acc0[1] + acc1[1] + acc2[1],
                        acc0[2] + acc1[2] + acc2[2],
                        acc0[3] + acc1[3] + acc2[3]);
        __syncthreads();

        // finalize (tid<256): sum 4 k-quarters, leaky update, stage packed
        if (tid < 256) {
            float s0 = scr[idx0] + scr[512 + idx0]
                     + scr[1024 + idx0] + scr[1536 + idx0];
            float s1 = scr[idx1] + scr[512 + idx1]
                     + scr[1024 + idx1] + scr[1536 + idx1];
            float hn0 = 0.9f * hr.x + 0.1f * fmaxf(z2.x + s0, 0.0f);
            float hn1 = 0.9f * hr.y + 0.1f * fmaxf(z2.y + s1, 0.0f);
            hr.x = hn0; hr.y = hn1;
            uint32_t hw, lw;
            split2(hn0, hn1, hw, lw);
            *(uint2*)&stg[stga] = make_uint2(hw, lw);
            z2.x = hn0; z2.y = hn1;
        }
        __syncthreads();

        // push slice to ranks rk0 and rk0+4 (buffer q)
        const uint32_t dOff = ((uint32_t)q * 4096u + slotW) * 4u;
        uint4 v4 = *(const uint4*)pSrc;
        #pragma unroll
        for (int i = 0; i < 2; i++) {
            int r = rk0 + i * 4;
            asm volatile("st.shared::cluster.v4.b32 [%0], {%1,%2,%3,%4};"
                         :: "r"(peerH[r] + dOff),
                            "r"(v4.x), "r"(v4.y), "r"(v4.z), "r"(v4.w)
                         : "memory");
        }
        asm volatile("barrier.cluster.arrive.aligned;" ::: "memory");

        // global stores in barrier-drain shadow
        if (tid < 256) {
            *(float2*)&hidden[off] = make_float2(z2.x, z2.y);
            if (t == LENGTH - 1)
                *(float2*)&hfinal[(size_t)bg * N_HID + absr] =
                    make_float2(z2.x, z2.y);
        }

        asm volatile("barrier.cluster.wait.aligned;" ::: "memory");
    }
}

extern "C" void kernel_launch(void* const* d_in, const int* in_sizes, int n_in,
                              void* d_out, int out_size) {
    const float* u    = (const float*)d_in[0];
    const float* h0   = (const float*)d_in[1];
    const float* Win  = (const float*)d_in[2];
    const float* bin  = (const float*)d_in[3];
    const float* Wih  = (const float*)d_in[4];
    const float* bih  = (const float*)d_in[5];
    const float* Whh  = (const float*)d_in[6];
    const float* bhh  = (const float*)d_in[7];
    const float* Wout = (const float*)d_in[8];
    const float* bout = (const float*)d_in[9];

    float* out     = (float*)d_out;
    float* hidden  = out;
    float* outlist = out + OUT_LIST_OFF;
    float* hfinal  = out + OUT_FINAL_OFF;

    weff_kernel<<<N_HID, 128>>>(Wih, Win, bin, bih, bhh);

    // Z = U @ W_eff^T + b_eff  (bf16x3 tensor GEMM)
    {
        float* dWeff; float* dbeff;
        cudaGetSymbolAddress((void**)&dWeff, g_Weff);
        cudaGetSymbolAddress((void**)&dbeff, g_beff);
        dim3 grid(M_ROWS / 128, N_HID / 64);
        gemm_bf16x3<<<grid, 256>>>(u, dWeff, dbeff, hidden,
                                   M_ROWS, N_HID, N_IN);
    }

    // recurrence
    {
        static int smem_set = 0;
        int smem = SM_WORDS * 4;   // 43008 B
        if (!smem_set) {
            cudaFuncSetAttribute(rec_kernel,
                                 cudaFuncAttributeMaxDynamicSharedMemorySize,
                                 smem);
            smem_set = 1;
        }
        for (int t0 = 0; t0 < LENGTH; t0 += T_SEG)
            rec_kernel<<<128, 512, smem>>>(Whh, h0, hidden, hfinal, t0);
    }

    // output_list = hidden_list @ W_out^T + b_out  (bf16x3 tensor GEMM)
    {
        dim3 grid(M_ROWS / 128, N_OUT / 64);
        gemm_bf16x3<<<grid, 256>>>(hidden, Wout, bout, outlist,
                                   M_ROWS, N_OUT, N_HID);
    }
}